// round 4
// baseline (speedup 1.0000x reference)
#include <cuda_runtime.h>
#include <cstddef>

#define NN 4096
#define FF 256
#define KK 8
#define FP 64
#define KF 512   // KK*FP

// ---------------- scratch (static device globals; no allocation) ----------------
__device__ float g_xe[NN * KF];     // 8 MB: xe[n][k*64+f]
__device__ float g_hl[KK * NN];
__device__ float g_hr[KK * NN];
__device__ float g_rm[KK * NN];     // row max of e (post-leaky)
__device__ unsigned g_or0, g_or1;
__device__ int g_code;              // 0=u8/bool, 1=int32, 2=float32

// ---------------- f32x2 packed-FMA helpers (FFMA2, 2x FFMA rate) ----------------
typedef unsigned long long u64;

__device__ __forceinline__ void ffma2(u64 &d, u64 a, u64 b) {
    asm("fma.rn.f32x2 %0, %1, %2, %0;" : "+l"(d) : "l"(a), "l"(b));
}
__device__ __forceinline__ u64 pack2dup(float v) {
    u64 r; asm("mov.b64 %0, {%1, %1};" : "=l"(r) : "f"(v)); return r;
}
__device__ __forceinline__ float2 unpack2(u64 d) {
    float2 r; asm("mov.b64 {%0, %1}, %2;" : "=f"(r.x), "=f"(r.y) : "l"(d)); return r;
}

// ---------------- mask accessor (dtype decided at runtime) ----------------
__device__ __forceinline__ unsigned mask_at(const void* m, int code, size_t idx) {
    if (code == 0)      return (unsigned)((const unsigned char*)m)[idx];
    else if (code == 1) return ((const int*)m)[idx] != 0;
    else                return __float_as_uint(((const float*)m)[idx]) != 0u;
}

// ---------------- K0: mask dtype detection ----------------
__global__ void k_zero() { g_or0 = 0u; g_or1 = 0u; }

__global__ void k_detect(const void* mask) {
    // Scan first 1 MB (safe: mask buffer is >= 16 MB in every dtype candidate).
    const unsigned* w = (const unsigned*)mask;
    unsigned o0 = 0u, o1 = 0u;
    int stride = gridDim.x * blockDim.x;
    for (int i = blockIdx.x * blockDim.x + threadIdx.x; i < (1 << 18); i += stride) {
        unsigned v = w[i];
        o0 |= (v & 0xFFu);          // byte offset 0 of each 4-byte group
        o1 |= ((v >> 8) & 0xFFu);   // byte offset 1
    }
    if (o0) atomicOr(&g_or0, o0);
    if (o1) atomicOr(&g_or1, o1);
}

__global__ void k_final() {
    // bool/u8: random 0/1 at every byte -> or1 != 0.
    // int32 0/1: byte1 always 0, byte0 sometimes 1 -> or1==0, or0!=0.
    // float32 0/1.0f: bytes 0,1 always 0 -> or0==or1==0.
    g_code = g_or1 ? 0 : (g_or0 ? 1 : 2);
}

// ---------------- K1: xe = x @ W^T + b  (M=4096, N=512, K=256) ----------------
__global__ void __launch_bounds__(256) gemm_xe(const float* __restrict__ x,
                                               const float* __restrict__ W,
                                               const float* __restrict__ b) {
    __shared__ float sA[16][68];   // [kk][m]
    __shared__ float sB[16][68];   // [kk][j]
    int tid = threadIdx.x;
    int tx = tid & 15, ty = tid >> 4;
    int row0 = blockIdx.y * 64;    // n
    int col0 = blockIdx.x * 64;    // j = k*64+f
    float acc[4][4];
#pragma unroll
    for (int i = 0; i < 4; i++)
#pragma unroll
        for (int j = 0; j < 4; j++) acc[i][j] = 0.f;

    for (int t = 0; t < FF / 16; t++) {
#pragma unroll
        for (int l = 0; l < 4; l++) {
            int idx = tid + l * 256;
            int mm = idx >> 4, kk = idx & 15;
            sA[kk][mm] = x[(size_t)(row0 + mm) * FF + t * 16 + kk];
            sB[kk][mm] = W[(size_t)(col0 + mm) * FF + t * 16 + kk];
        }
        __syncthreads();
#pragma unroll
        for (int kk = 0; kk < 16; kk++) {
            float a[4], bv[4];
#pragma unroll
            for (int i = 0; i < 4; i++) a[i] = sA[kk][ty * 4 + i];
#pragma unroll
            for (int j = 0; j < 4; j++) bv[j] = sB[kk][tx * 4 + j];
#pragma unroll
            for (int i = 0; i < 4; i++)
#pragma unroll
                for (int j = 0; j < 4; j++) acc[i][j] += a[i] * bv[j];
        }
        __syncthreads();
    }
#pragma unroll
    for (int i = 0; i < 4; i++)
#pragma unroll
        for (int j = 0; j < 4; j++) {
            int n = row0 + ty * 4 + i;
            int c = col0 + tx * 4 + j;
            g_xe[(size_t)n * KF + c] = acc[i][j] + b[c];
        }
}

// ---------------- K2: hl[k][n], hr[k][n] ----------------
__global__ void __launch_bounds__(256) k_hlr(const float* __restrict__ aL,
                                             const float* __restrict__ aR) {
    int lane = threadIdx.x & 31, warp = threadIdx.x >> 5;
    int n = blockIdx.x * 8 + warp;
    const float* xr = g_xe + (size_t)n * KF;
#pragma unroll
    for (int k = 0; k < KK; k++) {
        float x0 = xr[k * 64 + lane], x1 = xr[k * 64 + 32 + lane];
        float sl = x0 * aL[k * 64 + lane] + x1 * aL[k * 64 + 32 + lane];
        float sr = x0 * aR[k * 64 + lane] + x1 * aR[k * 64 + 32 + lane];
#pragma unroll
        for (int off = 16; off; off >>= 1) {
            sl += __shfl_xor_sync(0xffffffffu, sl, off);
            sr += __shfl_xor_sync(0xffffffffu, sr, off);
        }
        if (lane == 0) { g_hl[k * NN + n] = sl; g_hr[k * NN + n] = sr; }
    }
}

// ---------------- K3: row max via monotonicity of leaky-ReLU ----------------
// e[k,n,m] = leaky(hl[k,n]+hr[k,m]) is monotone in hr, so
// rowmax = leaky(hl + max_{m in mask(n)} hr[k,m]).
__global__ void __launch_bounds__(256) k_rowmax(const void* __restrict__ mask) {
    int code = g_code;
    int lane = threadIdx.x & 31, warp = threadIdx.x >> 5;
    int n = blockIdx.x * 8 + warp;
    float mx[KK];
#pragma unroll
    for (int k = 0; k < KK; k++) mx[k] = -1e30f;
    size_t rowbase = (size_t)n * NN;
    for (int mb = 0; mb < NN / 32; mb++) {
        int m = mb * 32 + lane;
        unsigned mk = mask_at(mask, code, rowbase + m);
#pragma unroll
        for (int k = 0; k < KK; k++) {
            float h = g_hr[k * NN + m];
            float c = mk ? h : -1e30f;
            mx[k] = fmaxf(mx[k], c);
        }
    }
#pragma unroll
    for (int k = 0; k < KK; k++) {
#pragma unroll
        for (int off = 16; off; off >>= 1)
            mx[k] = fmaxf(mx[k], __shfl_xor_sync(0xffffffffu, mx[k], off));
    }
    if (lane == 0) {
#pragma unroll
        for (int k = 0; k < KK; k++) {
            float e = g_hl[k * NN + n] + mx[k];
            e = fmaxf(e, 0.2f * e);          // leaky
            g_rm[k * NN + n] = e;
        }
    }
}

// ---------------- K4: fused attention (flash-style, f32x2 FMA) ----------------
#define TM 128
#define BK 32
__global__ void __launch_bounds__(128) k_attn(const void* __restrict__ mask,
                                              float* __restrict__ out) {
    int code = g_code;
    int k = blockIdx.y;
    int n0 = blockIdx.x * TM;
    int tid = threadIdx.x;
    int lane = tid & 31, wid = tid >> 5;

    __shared__ __align__(16) float s_xe[BK][FP];      // 8 KB
    __shared__ float s_p[BK][TM + 1];                 // stride 129 -> conflict-free STS
    __shared__ float s_hl[TM], s_rm[TM], s_sum[TM];

    if (tid < TM) {
        s_hl[tid] = g_hl[k * NN + n0 + tid];
        s_rm[tid] = g_rm[k * NN + n0 + tid];
        s_sum[tid] = 0.f;
    }

    u64 acc[8][4];
#pragma unroll
    for (int i = 0; i < 8; i++)
#pragma unroll
        for (int q = 0; q < 4; q++) acc[i][q] = 0ull;

    int tx = tid & 7;        // f-group (8 floats)
    int tyy = tid >> 3;      // 0..15 n-group
    int nb = tyy * 8;
    int fb = tx * 8;

    for (int mb = 0; mb < NN / BK; mb++) {
        int m0 = mb * BK;
        __syncthreads();   // previous GEMM done before overwriting tiles

        // --- stage xe tile: 32 rows x 64 f ---
#pragma unroll
        for (int l = 0; l < 4; l++) {
            int idx = tid + l * 128;
            int r = idx >> 4, c = (idx & 15) * 4;
            float4 v = *reinterpret_cast<const float4*>(
                &g_xe[(size_t)(m0 + r) * KF + k * FP + c]);
            *reinterpret_cast<float4*>(&s_xe[r][c]) = v;
        }

        // --- stage P tile: p[m][n] = mask ? exp(leaky(hl+hr) - rowmax) : 0 ---
        float hrm = g_hr[k * NN + m0 + lane];
#pragma unroll 4
        for (int j = 0; j < 32; j++) {
            int n = wid + 4 * j;                         // each warp owns n % 4 == wid
            unsigned mk = mask_at(mask, code, (size_t)(n0 + n) * NN + m0 + lane);
            float e = s_hl[n] + hrm;
            e = fmaxf(e, 0.2f * e);                      // leaky
            float p = mk ? __expf(e - s_rm[n]) : 0.0f;
            s_p[lane][n] = p;
            float ws = p;
#pragma unroll
            for (int off = 16; off; off >>= 1)
                ws += __shfl_xor_sync(0xffffffffu, ws, off);
            if (lane == 0) s_sum[n] += ws;               // unique n per warp -> race-free
        }
        __syncthreads();

        // --- GEMM: o[128][64] += p[128][32] @ xe[32][64], f32x2 packed ---
#pragma unroll 8
        for (int m = 0; m < BK; m++) {
            ulonglong2 x01 = *reinterpret_cast<const ulonglong2*>(&s_xe[m][fb]);
            ulonglong2 x23 = *reinterpret_cast<const ulonglong2*>(&s_xe[m][fb + 4]);
#pragma unroll
            for (int i = 0; i < 8; i++) {
                u64 pp = pack2dup(s_p[m][nb + i]);
                ffma2(acc[i][0], pp, x01.x);
                ffma2(acc[i][1], pp, x01.y);
                ffma2(acc[i][2], pp, x23.x);
                ffma2(acc[i][3], pp, x23.y);
            }
        }
    }
    __syncthreads();   // s_sum complete & visible

    // --- epilogue: normalize, double-ELU, store ---
#pragma unroll
    for (int i = 0; i < 8; i++) {
        int n = nb + i;
        float inv = 1.0f / s_sum[n];
        float r[8];
#pragma unroll
        for (int q = 0; q < 4; q++) {
            float2 v = unpack2(acc[i][q]);
            r[2 * q] = v.x * inv;
            r[2 * q + 1] = v.y * inv;
        }
#pragma unroll
        for (int t = 0; t < 8; t++) {
            float h = r[t];
            if (h <= 0.f) {
                h = __expf(h) - 1.0f;      // elu #1
                h = __expf(h) - 1.0f;      // elu #2 (input <= 0 here)
            }
            r[t] = h;
        }
        float4 o0 = make_float4(r[0], r[1], r[2], r[3]);
        float4 o1 = make_float4(r[4], r[5], r[6], r[7]);
        size_t base = (size_t)(n0 + n) * KF + k * FP + fb;
        *reinterpret_cast<float4*>(&out[base]) = o0;
        *reinterpret_cast<float4*>(&out[base + 4]) = o1;
    }
}

// ---------------- K5: write mask back as second tuple element (if expected) ----
__global__ void k_write_mask(const void* __restrict__ mask, float* __restrict__ out,
                             long extra) {
    int code = g_code;
    long stride = (long)gridDim.x * blockDim.x;
    for (long i = (long)blockIdx.x * blockDim.x + threadIdx.x; i < extra; i += stride) {
        float v = 0.f;
        if (i < (long)NN * NN) v = mask_at(mask, code, (size_t)i) ? 1.f : 0.f;
        out[(long)NN * KF + i] = v;
    }
}

// ---------------- launch ----------------
extern "C" void kernel_launch(void* const* d_in, const int* in_sizes, int n_in,
                              void* d_out, int out_size) {
    const float* x  = (const float*)d_in[0];
    const float* W  = (const float*)d_in[1];
    const float* b  = (const float*)d_in[2];
    const float* aL = (const float*)d_in[3];
    const float* aR = (const float*)d_in[4];
    const void*  mk = d_in[5];
    float* out = (float*)d_out;

    k_zero<<<1, 1>>>();
    k_detect<<<64, 256>>>(mk);
    k_final<<<1, 1>>>();

    dim3 g1(KF / 64, NN / 64);           // (8, 64)
    gemm_xe<<<g1, 256>>>(x, W, b);

    k_hlr<<<NN / 8, 256>>>(aL, aR);
    k_rowmax<<<NN / 8, 256>>>(mk);

    dim3 g4(NN / TM, KK);                // (32, 8)
    k_attn<<<g4, 128>>>(mk, out);

    long extra = (long)out_size - (long)NN * KF;
    if (extra > 0)
        k_write_mask<<<1024, 256>>>(mk, out, extra);
}

// round 6
// speedup vs baseline: 4.1859x; 4.1859x over previous
#include <cuda_runtime.h>
#include <cstddef>

#define NN 4096
#define FF 256
#define KK 8
#define FP 64
#define KF 512   // KK*FP

// ---------------- scratch (static device globals; no allocation) ----------------
__device__ float g_xe[NN * KF];     // 8 MB: xe[n][k*64+f]
__device__ float g_hl[KK * NN];
__device__ float g_hr[KK * NN];
__device__ float g_rm[KK * NN];     // row max of e (post-leaky)
__device__ unsigned g_or0, g_or1;
__device__ int g_code;              // 0=u8/bool, 1=int32, 2=float32

// ---------------- mask accessor (dtype decided at runtime) ----------------
__device__ __forceinline__ unsigned mask_at(const void* m, int code, size_t idx) {
    if (code == 0)      return (unsigned)((const unsigned char*)m)[idx];
    else if (code == 1) return ((const int*)m)[idx] != 0;
    else                return __float_as_uint(((const float*)m)[idx]) != 0u;
}

// ---------------- K0: mask dtype detection ----------------
__global__ void k_zero() { g_or0 = 0u; g_or1 = 0u; }

__global__ void k_detect(const void* mask) {
    const unsigned* w = (const unsigned*)mask;
    unsigned o0 = 0u, o1 = 0u;
    int stride = gridDim.x * blockDim.x;
    for (int i = blockIdx.x * blockDim.x + threadIdx.x; i < (1 << 18); i += stride) {
        unsigned v = w[i];
        o0 |= (v & 0xFFu);
        o1 |= ((v >> 8) & 0xFFu);
    }
    if (o0) atomicOr(&g_or0, o0);
    if (o1) atomicOr(&g_or1, o1);
}

__global__ void k_final() {
    // bool/u8: random 0/1 at every byte -> or1 != 0.
    // int32 0/1: byte1 always 0 -> or1==0, or0!=0.
    // float32 0/1.0f: bytes 0,1 always 0 -> or0==or1==0.
    g_code = g_or1 ? 0 : (g_or0 ? 1 : 2);
}

// ---------------- K1: xe = x @ W^T + b  (M=4096, N=512, K=256) ----------------
__global__ void __launch_bounds__(256) gemm_xe(const float* __restrict__ x,
                                               const float* __restrict__ W,
                                               const float* __restrict__ b) {
    __shared__ float sA[16][68];
    __shared__ float sB[16][68];
    int tid = threadIdx.x;
    int tx = tid & 15, ty = tid >> 4;
    int row0 = blockIdx.y * 64;
    int col0 = blockIdx.x * 64;
    float acc[4][4];
#pragma unroll
    for (int i = 0; i < 4; i++)
#pragma unroll
        for (int j = 0; j < 4; j++) acc[i][j] = 0.f;

    for (int t = 0; t < FF / 16; t++) {
#pragma unroll
        for (int l = 0; l < 4; l++) {
            int idx = tid + l * 256;
            int mm = idx >> 4, kk = idx & 15;
            sA[kk][mm] = x[(size_t)(row0 + mm) * FF + t * 16 + kk];
            sB[kk][mm] = W[(size_t)(col0 + mm) * FF + t * 16 + kk];
        }
        __syncthreads();
#pragma unroll
        for (int kk = 0; kk < 16; kk++) {
            float a[4], bv[4];
#pragma unroll
            for (int i = 0; i < 4; i++) a[i] = sA[kk][ty * 4 + i];
#pragma unroll
            for (int j = 0; j < 4; j++) bv[j] = sB[kk][tx * 4 + j];
#pragma unroll
            for (int i = 0; i < 4; i++)
#pragma unroll
                for (int j = 0; j < 4; j++) acc[i][j] += a[i] * bv[j];
        }
        __syncthreads();
    }
#pragma unroll
    for (int i = 0; i < 4; i++)
#pragma unroll
        for (int j = 0; j < 4; j++) {
            int n = row0 + ty * 4 + i;
            int c = col0 + tx * 4 + j;
            g_xe[(size_t)n * KF + c] = acc[i][j] + b[c];
        }
}

// ---------------- K2: hl[k][n], hr[k][n] ----------------
__global__ void __launch_bounds__(256) k_hlr(const float* __restrict__ aL,
                                             const float* __restrict__ aR) {
    int lane = threadIdx.x & 31, warp = threadIdx.x >> 5;
    int n = blockIdx.x * 8 + warp;
    const float* xr = g_xe + (size_t)n * KF;
#pragma unroll
    for (int k = 0; k < KK; k++) {
        float x0 = xr[k * 64 + lane], x1 = xr[k * 64 + 32 + lane];
        float sl = x0 * aL[k * 64 + lane] + x1 * aL[k * 64 + 32 + lane];
        float sr = x0 * aR[k * 64 + lane] + x1 * aR[k * 64 + 32 + lane];
#pragma unroll
        for (int off = 16; off; off >>= 1) {
            sl += __shfl_xor_sync(0xffffffffu, sl, off);
            sr += __shfl_xor_sync(0xffffffffu, sr, off);
        }
        if (lane == 0) { g_hl[k * NN + n] = sl; g_hr[k * NN + n] = sr; }
    }
}

// ---------------- K3: row max via monotonicity of leaky-ReLU ----------------
// e[k,n,m] = leaky(hl[k,n]+hr[k,m]) is monotone in hr, so
// rowmax = leaky(hl + max_{m in mask(n)} hr[k,m]).
__global__ void __launch_bounds__(256) k_rowmax(const void* __restrict__ mask) {
    int code = g_code;
    int lane = threadIdx.x & 31, warp = threadIdx.x >> 5;
    int n = blockIdx.x * 8 + warp;
    float mx[KK];
#pragma unroll
    for (int k = 0; k < KK; k++) mx[k] = -1e30f;
    size_t rowbase = (size_t)n * NN;
    for (int mb = 0; mb < NN / 32; mb++) {
        int m = mb * 32 + lane;
        unsigned mk = mask_at(mask, code, rowbase + m);
#pragma unroll
        for (int k = 0; k < KK; k++) {
            float h = g_hr[k * NN + m];
            float c = mk ? h : -1e30f;
            mx[k] = fmaxf(mx[k], c);
        }
    }
#pragma unroll
    for (int k = 0; k < KK; k++) {
#pragma unroll
        for (int off = 16; off; off >>= 1)
            mx[k] = fmaxf(mx[k], __shfl_xor_sync(0xffffffffu, mx[k], off));
    }
    if (lane == 0) {
#pragma unroll
        for (int k = 0; k < KK; k++) {
            float e = g_hl[k * NN + n] + mx[k];
            e = fmaxf(e, 0.2f * e);
            g_rm[k * NN + n] = e;
        }
    }
}

// ---------------- K4: fused attention (flash-style, tf32 mma.sync) ----------------
// Block: 256 threads (8 warps), handles (head k, 128 n-rows).
// Warp w owns rows [w*16, w*16+16); per m-tile of 32:
//   - stage xe[32][64] (tf32-rounded) and P[128][32] (tf32-rounded) in smem
//   - 4 k-steps x 8 n-tiles of mma.m16n8k8.tf32 per warp
// Row sums accumulate per-lane in registers (no per-tile shuffles).
#define TM 128
#define BK 32

__device__ __forceinline__ float tf32r(float v) {
    unsigned u; asm("cvt.rna.tf32.f32 %0, %1;" : "=r"(u) : "f"(v));
    return __uint_as_float(u);
}
__device__ __forceinline__ float elu2(float h) {
    if (h <= 0.f) {
        h = __expf(h) - 1.0f;      // elu #1
        h = __expf(h) - 1.0f;      // elu #2 (input <= 0 here)
    }
    return h;
}

__global__ void __launch_bounds__(256) k_attn(const void* __restrict__ mask,
                                              float* __restrict__ out) {
    int code = g_code;
    int k = blockIdx.y;
    int n0 = blockIdx.x * TM;
    int tid = threadIdx.x;
    int lane = tid & 31, w = tid >> 5;
    int gid = lane >> 2, tig = lane & 3;
    int row0 = w * 16;

    // pads chosen so mma-fragment LDS are bank-conflict-free:
    // s_p stride 36: bank=(4n+m)%32 distinct; s_xe stride 72: bank=(8k+c)%32 distinct
    __shared__ __align__(16) float s_xe[BK][72];
    __shared__ float s_p[TM][36];
    __shared__ float s_hl[TM], s_rm[TM], s_sum[TM];

    if (tid < TM) {
        s_hl[tid] = g_hl[k * NN + n0 + tid];
        s_rm[tid] = g_rm[k * NN + n0 + tid];
    }

    float acc[8][4];
#pragma unroll
    for (int t = 0; t < 8; t++)
#pragma unroll
        for (int q = 0; q < 4; q++) acc[t][q] = 0.f;
    float sumlane[16];
#pragma unroll
    for (int r = 0; r < 16; r++) sumlane[r] = 0.f;

    // xe staging coords: 8 floats per thread
    int sr = tid >> 3;            // 0..31 (m row)
    int sc = (tid & 7) * 8;       // 0..56 (f col)

    for (int mb = 0; mb < NN / BK; mb++) {
        int m0 = mb * BK;
        __syncthreads();   // prev tiles consumed (also covers hl/rm staging at mb=0)

        // --- stage xe tile [32][64], tf32-rounded ---
        {
            const float* src = &g_xe[(size_t)(m0 + sr) * KF + k * FP + sc];
            float4 v0 = *reinterpret_cast<const float4*>(src);
            float4 v1 = *reinterpret_cast<const float4*>(src + 4);
            s_xe[sr][sc + 0] = tf32r(v0.x);
            s_xe[sr][sc + 1] = tf32r(v0.y);
            s_xe[sr][sc + 2] = tf32r(v0.z);
            s_xe[sr][sc + 3] = tf32r(v0.w);
            s_xe[sr][sc + 4] = tf32r(v1.x);
            s_xe[sr][sc + 5] = tf32r(v1.y);
            s_xe[sr][sc + 6] = tf32r(v1.z);
            s_xe[sr][sc + 7] = tf32r(v1.w);
        }

        // --- stage P tile [128][32]: warp w rows row0..row0+15, lane = m ---
        float hr = g_hr[k * NN + m0 + lane];
#pragma unroll
        for (int r = 0; r < 16; r++) {
            int row = row0 + r;
            unsigned mk = mask_at(mask, code, (size_t)(n0 + row) * NN + m0 + lane);
            float e = s_hl[row] + hr;
            e = fmaxf(e, 0.2f * e);                       // leaky
            float p = mk ? __expf(e - s_rm[row]) : 0.0f;
            float pt = tf32r(p);
            s_p[row][lane] = pt;
            sumlane[r] += pt;                             // per-lane partial row sum
        }
        __syncthreads();

        // --- mma: o[16][64] += P[16][32] @ xe[32][64] per warp ---
#pragma unroll
        for (int ks = 0; ks < 4; ks++) {
            int kb = ks * 8;
            unsigned a0 = __float_as_uint(s_p[row0 + gid][kb + tig]);
            unsigned a1 = __float_as_uint(s_p[row0 + gid + 8][kb + tig]);
            unsigned a2 = __float_as_uint(s_p[row0 + gid][kb + tig + 4]);
            unsigned a3 = __float_as_uint(s_p[row0 + gid + 8][kb + tig + 4]);
#pragma unroll
            for (int t = 0; t < 8; t++) {
                unsigned b0 = __float_as_uint(s_xe[kb + tig][t * 8 + gid]);
                unsigned b1 = __float_as_uint(s_xe[kb + tig + 4][t * 8 + gid]);
                asm("mma.sync.aligned.m16n8k8.row.col.f32.tf32.tf32.f32 "
                    "{%0,%1,%2,%3}, {%4,%5,%6,%7}, {%8,%9}, {%0,%1,%2,%3};"
                    : "+f"(acc[t][0]), "+f"(acc[t][1]),
                      "+f"(acc[t][2]), "+f"(acc[t][3])
                    : "r"(a0), "r"(a1), "r"(a2), "r"(a3), "r"(b0), "r"(b1));
            }
        }
    }

    // --- reduce row sums (once) ---
#pragma unroll
    for (int r = 0; r < 16; r++) {
        float s = sumlane[r];
#pragma unroll
        for (int off = 16; off; off >>= 1)
            s += __shfl_xor_sync(0xffffffffu, s, off);
        if (lane == 0) s_sum[row0 + r] = s;
    }
    __syncthreads();

    // --- epilogue: normalize, double-ELU, store ---
    // c0,c1 -> row gid, cols 2*tig, 2*tig+1 ; c2,c3 -> row gid+8
#pragma unroll
    for (int half = 0; half < 2; half++) {
        int row = row0 + gid + half * 8;
        float inv = 1.0f / s_sum[row];
#pragma unroll
        for (int t = 0; t < 8; t++) {
            float va = elu2(acc[t][2 * half + 0] * inv);
            float vb = elu2(acc[t][2 * half + 1] * inv);
            size_t base = (size_t)(n0 + row) * KF + k * FP + t * 8 + 2 * tig;
            float2 o = make_float2(va, vb);
            *reinterpret_cast<float2*>(&out[base]) = o;
        }
    }
}

// ---------------- K5: write mask back as second tuple element (if expected) ----
__global__ void k_write_mask(const void* __restrict__ mask, float* __restrict__ out,
                             long extra) {
    int code = g_code;
    long stride = (long)gridDim.x * blockDim.x;
    for (long i = (long)blockIdx.x * blockDim.x + threadIdx.x; i < extra; i += stride) {
        float v = 0.f;
        if (i < (long)NN * NN) v = mask_at(mask, code, (size_t)i) ? 1.f : 0.f;
        out[(long)NN * KF + i] = v;
    }
}

// ---------------- launch ----------------
extern "C" void kernel_launch(void* const* d_in, const int* in_sizes, int n_in,
                              void* d_out, int out_size) {
    const float* x  = (const float*)d_in[0];
    const float* W  = (const float*)d_in[1];
    const float* b  = (const float*)d_in[2];
    const float* aL = (const float*)d_in[3];
    const float* aR = (const float*)d_in[4];
    const void*  mk = d_in[5];
    float* out = (float*)d_out;

    k_zero<<<1, 1>>>();
    k_detect<<<64, 256>>>(mk);
    k_final<<<1, 1>>>();

    dim3 g1(KF / 64, NN / 64);
    gemm_xe<<<g1, 256>>>(x, W, b);

    k_hlr<<<NN / 8, 256>>>(aL, aR);
    k_rowmax<<<NN / 8, 256>>>(mk);

    dim3 g4(NN / TM, KK);                // (32, 8)
    k_attn<<<g4, 256>>>(mk, out);

    long extra = (long)out_size - (long)NN * KF;
    if (extra > 0)
        k_write_mask<<<1024, 256>>>(mk, out, extra);
}

// round 7
// speedup vs baseline: 4.3546x; 1.0403x over previous
#include <cuda_runtime.h>
#include <cstddef>

#define NN 4096
#define FF 256
#define KK 8
#define FP 64
#define KF 512   // KK*FP

// ---------------- scratch (static device globals; no allocation) ----------------
__device__ float g_xe[NN * KF];     // 8 MB: xe[n][k*64+f]
__device__ float g_hl[KK * NN];
__device__ float g_hr[KK * NN];
__device__ float g_rm[KK * NN];     // row max of e (post-leaky)
__device__ unsigned g_or0, g_or1;
__device__ int g_code;              // 0=u8/bool, 1=int32, 2=float32

// ---------------- mask accessor (dtype decided at runtime) ----------------
__device__ __forceinline__ unsigned mask_at(const void* m, int code, size_t idx) {
    if (code == 0)      return (unsigned)((const unsigned char*)m)[idx];
    else if (code == 1) return ((const int*)m)[idx] != 0;
    else                return __float_as_uint(((const float*)m)[idx]) != 0u;
}

// ---------------- K0: mask dtype detection ----------------
__global__ void k_zero() { g_or0 = 0u; g_or1 = 0u; }

__global__ void k_detect(const void* mask) {
    const unsigned* w = (const unsigned*)mask;
    unsigned o0 = 0u, o1 = 0u;
    int stride = gridDim.x * blockDim.x;
    for (int i = blockIdx.x * blockDim.x + threadIdx.x; i < (1 << 18); i += stride) {
        unsigned v = w[i];
        o0 |= (v & 0xFFu);
        o1 |= ((v >> 8) & 0xFFu);
    }
    if (o0) atomicOr(&g_or0, o0);
    if (o1) atomicOr(&g_or1, o1);
}

__global__ void k_final() {
    // bool/u8: random 0/1 at every byte -> or1 != 0.
    // int32 0/1: byte1 always 0 -> or1==0, or0!=0.
    // float32 0/1.0f: bytes 0,1 always 0 -> or0==or1==0.
    g_code = g_or1 ? 0 : (g_or0 ? 1 : 2);
}

// ---------------- K1: xe = x @ W^T + b  (M=4096, N=512, K=256) ----------------
__global__ void __launch_bounds__(256) gemm_xe(const float* __restrict__ x,
                                               const float* __restrict__ W,
                                               const float* __restrict__ b) {
    __shared__ float sA[16][68];
    __shared__ float sB[16][68];
    int tid = threadIdx.x;
    int tx = tid & 15, ty = tid >> 4;
    int row0 = blockIdx.y * 64;
    int col0 = blockIdx.x * 64;
    float acc[4][4];
#pragma unroll
    for (int i = 0; i < 4; i++)
#pragma unroll
        for (int j = 0; j < 4; j++) acc[i][j] = 0.f;

    for (int t = 0; t < FF / 16; t++) {
#pragma unroll
        for (int l = 0; l < 4; l++) {
            int idx = tid + l * 256;
            int mm = idx >> 4, kk = idx & 15;
            sA[kk][mm] = x[(size_t)(row0 + mm) * FF + t * 16 + kk];
            sB[kk][mm] = W[(size_t)(col0 + mm) * FF + t * 16 + kk];
        }
        __syncthreads();
#pragma unroll
        for (int kk = 0; kk < 16; kk++) {
            float a[4], bv[4];
#pragma unroll
            for (int i = 0; i < 4; i++) a[i] = sA[kk][ty * 4 + i];
#pragma unroll
            for (int j = 0; j < 4; j++) bv[j] = sB[kk][tx * 4 + j];
#pragma unroll
            for (int i = 0; i < 4; i++)
#pragma unroll
                for (int j = 0; j < 4; j++) acc[i][j] += a[i] * bv[j];
        }
        __syncthreads();
    }
#pragma unroll
    for (int i = 0; i < 4; i++)
#pragma unroll
        for (int j = 0; j < 4; j++) {
            int n = row0 + ty * 4 + i;
            int c = col0 + tx * 4 + j;
            g_xe[(size_t)n * KF + c] = acc[i][j] + b[c];
        }
}

// ---------------- K2: hl[k][n], hr[k][n] ----------------
__global__ void __launch_bounds__(256) k_hlr(const float* __restrict__ aL,
                                             const float* __restrict__ aR) {
    int lane = threadIdx.x & 31, warp = threadIdx.x >> 5;
    int n = blockIdx.x * 8 + warp;
    const float* xr = g_xe + (size_t)n * KF;
#pragma unroll
    for (int k = 0; k < KK; k++) {
        float x0 = xr[k * 64 + lane], x1 = xr[k * 64 + 32 + lane];
        float sl = x0 * aL[k * 64 + lane] + x1 * aL[k * 64 + 32 + lane];
        float sr = x0 * aR[k * 64 + lane] + x1 * aR[k * 64 + 32 + lane];
#pragma unroll
        for (int off = 16; off; off >>= 1) {
            sl += __shfl_xor_sync(0xffffffffu, sl, off);
            sr += __shfl_xor_sync(0xffffffffu, sr, off);
        }
        if (lane == 0) { g_hl[k * NN + n] = sl; g_hr[k * NN + n] = sr; }
    }
}

// ---------------- K3: row max via monotonicity of leaky-ReLU ----------------
// e[k,n,m] = leaky(hl[k,n]+hr[k,m]) is monotone in hr, so
// rowmax = leaky(hl + max_{m in mask(n)} hr[k,m]).
__global__ void __launch_bounds__(256) k_rowmax(const void* __restrict__ mask) {
    int code = g_code;
    int lane = threadIdx.x & 31, warp = threadIdx.x >> 5;
    int n = blockIdx.x * 8 + warp;
    float mx[KK];
#pragma unroll
    for (int k = 0; k < KK; k++) mx[k] = -1e30f;
    size_t rowbase = (size_t)n * NN;
    for (int mb = 0; mb < NN / 32; mb++) {
        int m = mb * 32 + lane;
        unsigned mk = mask_at(mask, code, rowbase + m);
#pragma unroll
        for (int k = 0; k < KK; k++) {
            float h = g_hr[k * NN + m];
            float c = mk ? h : -1e30f;
            mx[k] = fmaxf(mx[k], c);
        }
    }
#pragma unroll
    for (int k = 0; k < KK; k++) {
#pragma unroll
        for (int off = 16; off; off >>= 1)
            mx[k] = fmaxf(mx[k], __shfl_xor_sync(0xffffffffu, mx[k], off));
    }
    if (lane == 0) {
#pragma unroll
        for (int k = 0; k < KK; k++) {
            float e = g_hl[k * NN + n] + mx[k];
            e = fmaxf(e, 0.2f * e);
            g_rm[k * NN + n] = e;
        }
    }
}

// ---------------- K4: fused attention (tf32 mma.sync, double-buffered) ----------
// Block: 128 threads (4 warps), handles (head k, 64 n-rows). Warp w owns rows
// [w*16, w*16+16). Pipeline: stage tile mb+1 into buffer ^1 while issuing mma
// on tile mb; one __syncthreads per tile. Mask LDGs front-batched for MLP.
#define TM 64
#define BK 32
#define NT (NN / BK)

__device__ __forceinline__ float elu2(float h) {
    if (h <= 0.f) {
        h = __expf(h) - 1.0f;      // elu #1
        h = __expf(h) - 1.0f;      // elu #2 (input <= 0 here)
    }
    return h;
}

// stage one (xe, P) tile pair into the given buffers
__device__ __forceinline__ void stage_tile(
    int m0, float (*sxe)[72], float (*sp)[36],
    const float* s_hl, const float* s_rm, float* sumlane,
    const void* mask, int code, int k, int n0, int tid, int lane, int row0)
{
    // --- xe tile [32][64]: 128 threads x 16 floats (no cvt: HMMA truncates) ---
    int sr = tid >> 2;             // 0..31 (m row)
    int sc = (tid & 3) * 16;       // 0,16,32,48
    const float* src = &g_xe[(size_t)(m0 + sr) * KF + k * FP + sc];
    float4 v0 = *reinterpret_cast<const float4*>(src);
    float4 v1 = *reinterpret_cast<const float4*>(src + 4);
    float4 v2 = *reinterpret_cast<const float4*>(src + 8);
    float4 v3 = *reinterpret_cast<const float4*>(src + 12);
    *reinterpret_cast<float4*>(&sxe[sr][sc + 0])  = v0;
    *reinterpret_cast<float4*>(&sxe[sr][sc + 4])  = v1;
    *reinterpret_cast<float4*>(&sxe[sr][sc + 8])  = v2;
    *reinterpret_cast<float4*>(&sxe[sr][sc + 12]) = v3;

    // --- P tile: warp rows row0..row0+15, lane = m; batch mask loads (MLP 16) ---
    unsigned mk[16];
#pragma unroll
    for (int r = 0; r < 16; r++)
        mk[r] = mask_at(mask, code, (size_t)(n0 + row0 + r) * NN + m0 + lane);
    float hr = g_hr[k * NN + m0 + lane];
#pragma unroll
    for (int r = 0; r < 16; r++) {
        int row = row0 + r;
        float e = s_hl[row] + hr;
        e = fmaxf(e, 0.2f * e);                       // leaky
        float p = mk[r] ? __expf(e - s_rm[row]) : 0.0f;
        sp[row][lane] = p;
        sumlane[r] += p;                              // per-lane partial row sum
    }
}

__global__ void __launch_bounds__(128) k_attn(const void* __restrict__ mask,
                                              float* __restrict__ out) {
    int code = g_code;
    int k = blockIdx.y;
    int n0 = blockIdx.x * TM;
    int tid = threadIdx.x;
    int lane = tid & 31, w = tid >> 5;
    int gid = lane >> 2, tig = lane & 3;
    int row0 = w * 16;

    // pads: s_p stride 36 -> bank=(4n+m)%32 distinct; s_xe stride 72 -> (8k+c)%32 distinct
    __shared__ __align__(16) float s_xe[2][BK][72];   // 18 KB
    __shared__ float s_p[2][TM][36];                  // 18 KB
    __shared__ float s_hl[TM], s_rm[TM], s_sum[TM];

    if (tid < TM) {
        s_hl[tid] = g_hl[k * NN + n0 + tid];
        s_rm[tid] = g_rm[k * NN + n0 + tid];
    }
    __syncthreads();   // s_hl/s_rm visible before first stage

    float acc[8][4];
#pragma unroll
    for (int t = 0; t < 8; t++)
#pragma unroll
        for (int q = 0; q < 4; q++) acc[t][q] = 0.f;
    float sumlane[16];
#pragma unroll
    for (int r = 0; r < 16; r++) sumlane[r] = 0.f;

    // prologue: stage tile 0 into buffer 0
    stage_tile(0, s_xe[0], s_p[0], s_hl, s_rm, sumlane,
               mask, code, k, n0, tid, lane, row0);

    for (int mb = 0; mb < NT; mb++) {
        int cur = mb & 1;
        __syncthreads();   // staging of cur visible; prior mma on cur^1 done

        // stage next tile into the other buffer (overlaps with mma below)
        if (mb + 1 < NT)
            stage_tile((mb + 1) * BK, s_xe[cur ^ 1], s_p[cur ^ 1],
                       s_hl, s_rm, sumlane, mask, code, k, n0, tid, lane, row0);

        // --- mma: o[16][64] += P[16][32] @ xe[32][64] per warp ---
#pragma unroll
        for (int ks = 0; ks < 4; ks++) {
            int kb = ks * 8;
            unsigned a0 = __float_as_uint(s_p[cur][row0 + gid][kb + tig]);
            unsigned a1 = __float_as_uint(s_p[cur][row0 + gid + 8][kb + tig]);
            unsigned a2 = __float_as_uint(s_p[cur][row0 + gid][kb + tig + 4]);
            unsigned a3 = __float_as_uint(s_p[cur][row0 + gid + 8][kb + tig + 4]);
#pragma unroll
            for (int t = 0; t < 8; t++) {
                unsigned b0 = __float_as_uint(s_xe[cur][kb + tig][t * 8 + gid]);
                unsigned b1 = __float_as_uint(s_xe[cur][kb + tig + 4][t * 8 + gid]);
                asm("mma.sync.aligned.m16n8k8.row.col.f32.tf32.tf32.f32 "
                    "{%0,%1,%2,%3}, {%4,%5,%6,%7}, {%8,%9}, {%0,%1,%2,%3};"
                    : "+f"(acc[t][0]), "+f"(acc[t][1]),
                      "+f"(acc[t][2]), "+f"(acc[t][3])
                    : "r"(a0), "r"(a1), "r"(a2), "r"(a3), "r"(b0), "r"(b1));
            }
        }
    }

    // --- reduce row sums (once) ---
#pragma unroll
    for (int r = 0; r < 16; r++) {
        float s = sumlane[r];
#pragma unroll
        for (int off = 16; off; off >>= 1)
            s += __shfl_xor_sync(0xffffffffu, s, off);
        if (lane == 0) s_sum[row0 + r] = s;
    }
    __syncthreads();

    // --- epilogue: normalize, double-ELU, store ---
    // c0,c1 -> row gid, cols 2*tig, 2*tig+1 ; c2,c3 -> row gid+8
#pragma unroll
    for (int half = 0; half < 2; half++) {
        int row = row0 + gid + half * 8;
        float inv = 1.0f / s_sum[row];
#pragma unroll
        for (int t = 0; t < 8; t++) {
            float va = elu2(acc[t][2 * half + 0] * inv);
            float vb = elu2(acc[t][2 * half + 1] * inv);
            size_t base = (size_t)(n0 + row) * KF + k * FP + t * 8 + 2 * tig;
            float2 o = make_float2(va, vb);
            *reinterpret_cast<float2*>(&out[base]) = o;
        }
    }
}

// ---------------- K5: write mask back as second tuple element (if expected) ----
__global__ void k_write_mask(const void* __restrict__ mask, float* __restrict__ out,
                             long extra) {
    int code = g_code;
    long stride = (long)gridDim.x * blockDim.x;
    for (long i = (long)blockIdx.x * blockDim.x + threadIdx.x; i < extra; i += stride) {
        float v = 0.f;
        if (i < (long)NN * NN) v = mask_at(mask, code, (size_t)i) ? 1.f : 0.f;
        out[(long)NN * KF + i] = v;
    }
}

// ---------------- launch ----------------
extern "C" void kernel_launch(void* const* d_in, const int* in_sizes, int n_in,
                              void* d_out, int out_size) {
    const float* x  = (const float*)d_in[0];
    const float* W  = (const float*)d_in[1];
    const float* b  = (const float*)d_in[2];
    const float* aL = (const float*)d_in[3];
    const float* aR = (const float*)d_in[4];
    const void*  mk = d_in[5];
    float* out = (float*)d_out;

    k_zero<<<1, 1>>>();
    k_detect<<<64, 256>>>(mk);
    k_final<<<1, 1>>>();

    dim3 g1(KF / 64, NN / 64);
    gemm_xe<<<g1, 256>>>(x, W, b);

    k_hlr<<<NN / 8, 256>>>(aL, aR);
    k_rowmax<<<NN / 8, 256>>>(mk);

    dim3 g4(NN / TM, KK);                // (64, 8) = 512 CTAs
    k_attn<<<g4, 128>>>(mk, out);

    long extra = (long)out_size - (long)NN * KF;
    if (extra > 0)
        k_write_mask<<<1024, 256>>>(mk, out, extra);
}